// round 6
// baseline (speedup 1.0000x reference)
#include <cuda_runtime.h>
#include <mma.h>
using namespace nvcuda;

#define B_    16
#define TQ_   128
#define TK_   128
#define EMB_  256
#define HID_  100
#define F2E_  512   // 2*EMB

// Scratch (allocation-free rule: __device__ globals)
__device__ float g_A[B_ * TK_ * HID_];        // A[b][i][h]
__device__ float g_Ct[B_ * HID_ * TQ_];       // C^T[b][h][j]  (includes +b1)
__device__ float g_feat[B_ * TK_ * F2E_];     // [row][f]
__device__ float g_W1p[128 * F2E_];           // W1 zero-padded to 128 rows

__device__ __forceinline__ float ftanh(float x) {
    float y;
    asm("tanh.approx.f32 %0, %1;" : "=f"(y) : "f"(x));
    return y;
}

// ---------------------------------------------------------------------------
// K0: pad W1 [100,512] -> g_W1p [128,512] (zero rows 100..127)
// ---------------------------------------------------------------------------
__global__ void pad_w1(const float* __restrict__ W1) {
    int i = blockIdx.x * 256 + threadIdx.x;     // 65536 total
    int h = i >> 9;
    g_W1p[i] = (h < HID_) ? W1[i - (h << 9) + h * F2E_] : 0.f;
}

// ---------------------------------------------------------------------------
// 3xTF32 fragment split helper (fp32-grade accuracy on tensor pipe)
// ---------------------------------------------------------------------------
template <typename Frag>
__device__ __forceinline__ void split3(Frag& hi, Frag& lo) {
    #pragma unroll
    for (int i = 0; i < hi.num_elements; ++i) {
        float v = hi.x[i];
        float h = wmma::__float_to_tf32(v);
        hi.x[i] = h;
        lo.x[i] = wmma::__float_to_tf32(v - h);
    }
}

#define LDC 36  // epilogue smem stride

// ---------------------------------------------------------------------------
// K1: prep GEMM (tensor cores, 3xTF32).
// Fused M=4096 (rows<2048: keys->A w/ W1[:,:256]; else queries->Ct + b1).
// BM=64, BN=32, 256 threads (8 warps: wm=w&3 m-quarter, wn=w>>2 n-half),
// each warp one 16x16 tile. grid (4 n-tiles, 64 m-tiles) = 256 blocks.
// ---------------------------------------------------------------------------
__global__ void __launch_bounds__(256) prep_wmma(
        const float* __restrict__ queries,
        const float* __restrict__ keys,
        const float* __restrict__ b1) {
    __shared__ float cs[64 * LDC];
    int m0g = blockIdx.y * 64;
    int side = m0g >= (B_ * TK_);
    int m0 = m0g & (B_ * TK_ - 1);
    int n0 = blockIdx.x * 32;
    const float* X = side ? queries : keys;
    const float* Bbase = g_W1p + side * EMB_;

    int w = threadIdx.x >> 5;
    int wm = w & 3, wn = w >> 2;
    const float* Aptr = X + (m0 + wm * 16) * EMB_;
    const float* Bptr = Bbase + (n0 + wn * 16) * F2E_;

    wmma::fragment<wmma::accumulator, 16, 16, 8, float> c;
    wmma::fill_fragment(c, 0.f);
    wmma::fragment<wmma::matrix_a, 16, 16, 8, wmma::precision::tf32,
                   wmma::row_major> a_hi, a_lo;
    wmma::fragment<wmma::matrix_b, 16, 16, 8, wmma::precision::tf32,
                   wmma::col_major> b_hi, b_lo;

    #pragma unroll 4
    for (int k = 0; k < EMB_; k += 8) {
        wmma::load_matrix_sync(a_hi, Aptr + k, EMB_);
        split3(a_hi, a_lo);
        wmma::load_matrix_sync(b_hi, Bptr + k, F2E_);
        split3(b_hi, b_lo);
        wmma::mma_sync(c, a_lo, b_hi, c);
        wmma::mma_sync(c, a_hi, b_lo, c);
        wmma::mma_sync(c, a_hi, b_hi, c);
    }

    wmma::store_matrix_sync(cs + (wm * 16) * LDC + wn * 16, c, LDC,
                            wmma::mem_row_major);
    __syncthreads();

    int tid = threadIdx.x;
    for (int e = tid; e < 64 * 32; e += 256) {
        int r = e >> 5, col = e & 31;
        int h = n0 + col;
        if (h < HID_) {
            float v = cs[r * LDC + col];
            int row = m0 + r;
            if (!side) {
                g_A[row * HID_ + h] = v;
            } else {
                int b = row >> 7, j = row & 127;
                g_Ct[(b * HID_ + h) * TQ_ + j] = v + b1[h];
            }
        }
    }
}

// ---------------------------------------------------------------------------
// K2: fused score MLP + softmax + attention + feature build (R4 version).
// One block per (b, 8-row i-tile): grid (16, 16) = 256 blocks, 256 threads.
// ---------------------------------------------------------------------------
#define ITILE 8
#define PSTR  12

__global__ void __launch_bounds__(256) attn_kernel(
        const float* __restrict__ queries,
        const float* __restrict__ keys,
        const float* __restrict__ qmask,
        const float* __restrict__ kmask,
        const float* __restrict__ W2) {
    extern __shared__ __align__(16) float sm[];
    float* c_s  = sm;                        // 12800
    float* a_s  = c_s + HID_ * TQ_;          // 800
    float* p_s  = a_s + ITILE * HID_;        // 1536
    float* w2_s = p_s + TQ_ * PSTR;          // 104
    float* km_s = w2_s + 104;                // 8

    int b  = blockIdx.y;
    int i0 = blockIdx.x * ITILE;
    int tid = threadIdx.x;

    {
        const float4* src = (const float4*)(g_Ct + b * HID_ * TQ_);
        float4* dst = (float4*)c_s;
        for (int idx = tid; idx < (HID_ * TQ_) / 4; idx += 256)
            dst[idx] = src[idx];
    }
    for (int idx = tid; idx < ITILE * HID_; idx += 256)
        a_s[idx] = g_A[(b * TK_ + i0) * HID_ + idx];
    if (tid < HID_)  w2_s[tid] = W2[tid];
    if (tid < ITILE) km_s[tid] = kmask[b * TK_ + i0 + tid];

    int j = tid & 127;        // query position
    int g = tid >> 7;         // i-row parity (0/1)
    float qm = qmask[b * TQ_ + j];
    __syncthreads();

    // ---- phase 1: sim[ii][j] = sum_h tanh(a[ii,h] + c[h,j]) * w2[h]
    float acc[4];
    #pragma unroll
    for (int r = 0; r < 4; ++r) acc[r] = 0.f;
    for (int h = 0; h < HID_; ++h) {
        float cj = c_s[h * TQ_ + j];
        float w  = w2_s[h];
        #pragma unroll
        for (int r = 0; r < 4; ++r) {
            float x = a_s[(g + 2 * r) * HID_ + h] + cj;
            acc[r] = fmaf(w, ftanh(x), acc[r]);
        }
    }
    const float NEGC = -4294967295.0f;  // -2^32 + 1
    #pragma unroll
    for (int r = 0; r < 4; ++r)
        p_s[j * PSTR + (g + 2 * r)] = (qm == 0.0f) ? NEGC : acc[r];
    __syncthreads();

    // ---- phase 2: softmax over j; warp w owns row w (8 warps, 8 rows)
    int warp = tid >> 5, lane = tid & 31;
    {
        int ii = warp;
        float v[4];
        float m = -3.4e38f;
        #pragma unroll
        for (int q = 0; q < 4; ++q) {
            v[q] = p_s[(lane + 32 * q) * PSTR + ii];
            m = fmaxf(m, v[q]);
        }
        #pragma unroll
        for (int off = 16; off; off >>= 1)
            m = fmaxf(m, __shfl_xor_sync(0xffffffffu, m, off));
        float ssum = 0.f;
        #pragma unroll
        for (int q = 0; q < 4; ++q) { v[q] = __expf(v[q] - m); ssum += v[q]; }
        #pragma unroll
        for (int off = 16; off; off >>= 1)
            ssum += __shfl_xor_sync(0xffffffffu, ssum, off);
        float scale = km_s[ii] / ssum;   // fold key_mask scalar into p
        #pragma unroll
        for (int q = 0; q < 4; ++q)
            p_s[(lane + 32 * q) * PSTR + ii] = v[q] * scale;
    }
    __syncthreads();

    // ---- phase 3: keys_attn[ii,e] = sum_j p[ii,j] * q[b,j,e]; then features
    int e = tid;  // 0..255
    float ka[ITILE];
    #pragma unroll
    for (int r = 0; r < ITILE; ++r) ka[r] = 0.f;
    const float* qb = queries + b * TQ_ * EMB_ + e;
    #pragma unroll 4
    for (int jj = 0; jj < TQ_; ++jj) {
        float qv = qb[jj * EMB_];
        float pv[ITILE];
        *(float4*)&pv[0] = *(const float4*)&p_s[jj * PSTR + 0];
        *(float4*)&pv[4] = *(const float4*)&p_s[jj * PSTR + 4];
        #pragma unroll
        for (int r = 0; r < ITILE; ++r)
            ka[r] = fmaf(pv[r], qv, ka[r]);
    }
    #pragma unroll
    for (int r = 0; r < ITILE; ++r) {
        int rowg = b * TK_ + i0 + r;
        float kv = keys[rowg * EMB_ + e];
        float fm = ka[r] * kv;
        float d  = ka[r] - kv;
        g_feat[rowg * F2E_ + e]        = fm;
        g_feat[rowg * F2E_ + EMB_ + e] = d * d;
    }
}

// ---------------------------------------------------------------------------
// K3: out = relu(feat[2048,512] @ Wlast[256,512]^T + blast), tensor cores.
// BM=64, BN=32, 256 threads, grid (8, 32) = 256 blocks.
// ---------------------------------------------------------------------------
__global__ void __launch_bounds__(256) gemm_wmma(
        const float* __restrict__ Wlast,
        const float* __restrict__ blast,
        float* __restrict__ out) {
    __shared__ float cs[64 * LDC];
    int m0 = blockIdx.y * 64;
    int n0 = blockIdx.x * 32;

    int w = threadIdx.x >> 5;
    int wm = w & 3, wn = w >> 2;
    const float* Aptr = g_feat + (m0 + wm * 16) * F2E_;
    const float* Bptr = Wlast + (n0 + wn * 16) * F2E_;

    wmma::fragment<wmma::accumulator, 16, 16, 8, float> c;
    wmma::fill_fragment(c, 0.f);
    wmma::fragment<wmma::matrix_a, 16, 16, 8, wmma::precision::tf32,
                   wmma::row_major> a_hi, a_lo;
    wmma::fragment<wmma::matrix_b, 16, 16, 8, wmma::precision::tf32,
                   wmma::col_major> b_hi, b_lo;

    #pragma unroll 4
    for (int k = 0; k < F2E_; k += 8) {
        wmma::load_matrix_sync(a_hi, Aptr + k, F2E_);
        split3(a_hi, a_lo);
        wmma::load_matrix_sync(b_hi, Bptr + k, F2E_);
        split3(b_hi, b_lo);
        wmma::mma_sync(c, a_lo, b_hi, c);
        wmma::mma_sync(c, a_hi, b_lo, c);
        wmma::mma_sync(c, a_hi, b_hi, c);
    }

    wmma::store_matrix_sync(cs + (wm * 16) * LDC + wn * 16, c, LDC,
                            wmma::mem_row_major);
    __syncthreads();

    int tid = threadIdx.x;
    for (int e = tid; e < 64 * 32; e += 256) {
        int r = e >> 5, col = e & 31;
        float v = cs[r * LDC + col] + blast[n0 + col];
        out[(m0 + r) * EMB_ + n0 + col] = fmaxf(v, 0.f);
    }
}

// ---------------------------------------------------------------------------
extern "C" void kernel_launch(void* const* d_in, const int* in_sizes, int n_in,
                              void* d_out, int out_size) {
    const float* queries = (const float*)d_in[0];
    const float* keys    = (const float*)d_in[1];
    const float* qmask   = (const float*)d_in[2];
    const float* kmask   = (const float*)d_in[3];
    const float* W1      = (const float*)d_in[4];
    const float* b1      = (const float*)d_in[5];
    const float* W2      = (const float*)d_in[6];
    const float* Wlast   = (const float*)d_in[7];
    const float* blast   = (const float*)d_in[8];
    float* out = (float*)d_out;

    const int smem_attn = (HID_ * TQ_ + ITILE * HID_ + TQ_ * PSTR + 104 + ITILE) * 4;
    cudaFuncSetAttribute(attn_kernel, cudaFuncAttributeMaxDynamicSharedMemorySize,
                         smem_attn);

    pad_w1<<<256, 256>>>(W1);
    prep_wmma<<<dim3(4, (2 * B_ * TK_) / 64), 256>>>(queries, keys, b1);
    attn_kernel<<<dim3(TK_ / ITILE, B_), 256, smem_attn>>>(queries, keys, qmask,
                                                           kmask, W2);
    gemm_wmma<<<dim3(EMB_ / 32, (B_ * TK_) / 64), 256>>>(Wlast, blast, out);
}

// round 7
// speedup vs baseline: 1.0555x; 1.0555x over previous
#include <cuda_runtime.h>
#include <mma.h>
using namespace nvcuda;

#define B_    16
#define TQ_   128
#define TK_   128
#define EMB_  256
#define HID_  100
#define F2E_  512   // 2*EMB

// Scratch (allocation-free rule: __device__ globals)
__device__ float g_A[B_ * TK_ * HID_];        // A[b][i][h]
__device__ float g_Ct[B_ * HID_ * TQ_];       // C^T[b][h][j]  (includes +b1)
__device__ float g_feat[B_ * TK_ * F2E_];     // [row][f]
__device__ float g_W1p[128 * F2E_];           // W1 zero-padded to 128 rows

__device__ __forceinline__ float ftanh(float x) {
    float y;
    asm("tanh.approx.f32 %0, %1;" : "=f"(y) : "f"(x));
    return y;
}

// ---------------------------------------------------------------------------
// K0: pad W1 [100,512] -> g_W1p [128,512] (zero rows 100..127)
// ---------------------------------------------------------------------------
__global__ void pad_w1(const float* __restrict__ W1) {
    int i = blockIdx.x * 256 + threadIdx.x;     // 65536 total
    int h = i >> 9;
    g_W1p[i] = (h < HID_) ? W1[i] : 0.f;
}

// ---------------------------------------------------------------------------
// 3xTF32 fragment split helper (fp32-grade accuracy on tensor pipe)
// ---------------------------------------------------------------------------
template <typename Frag>
__device__ __forceinline__ void split3(Frag& hi, Frag& lo) {
    #pragma unroll
    for (int i = 0; i < hi.num_elements; ++i) {
        float v = hi.x[i];
        float h = wmma::__float_to_tf32(v);
        hi.x[i] = h;
        lo.x[i] = wmma::__float_to_tf32(v - h);
    }
}

#define TLD 20   // smem tile stride (floats): 80B, 16B-aligned rows, ldm%4==0
#define CLD 68   // epilogue C stride

// Shared GEMM macro body: computes C[64x64] = A[64xK] * B[64xK]^T for one
// block tile, smem-staged, double-buffered, 3xTF32. Caller supplies aptr/bptr
// (this thread's float4 source pointers), LDA/LDB strides, NT tile count,
// then consumes cs[].
#define GEMM_BODY(APTR, LDA, BPTR, LDB, NT)                                    \
    int tid = threadIdx.x;                                                     \
    int r = tid >> 2, c4 = (tid & 3) * 4;                                      \
    int w = tid >> 5, wm = w & 1, wn = w >> 1;                                 \
    wmma::fragment<wmma::accumulator, 16, 16, 8, float> c0, c1;                \
    wmma::fill_fragment(c0, 0.f);                                              \
    wmma::fill_fragment(c1, 0.f);                                              \
    wmma::fragment<wmma::matrix_a, 16, 16, 8, wmma::precision::tf32,           \
                   wmma::row_major> a_hi, a_lo;                                \
    wmma::fragment<wmma::matrix_b, 16, 16, 8, wmma::precision::tf32,           \
                   wmma::col_major> b_hi, b_lo;                                \
    float4 av = *(const float4*)((APTR));                                      \
    float4 bv = *(const float4*)((BPTR));                                      \
    *(float4*)&As[0][r * TLD + c4] = av;                                       \
    *(float4*)&Bs[0][r * TLD + c4] = bv;                                       \
    __syncthreads();                                                           \
    _Pragma("unroll 1")                                                        \
    for (int t = 0; t < (NT); ++t) {                                           \
        if (t + 1 < (NT)) {                                                    \
            av = *(const float4*)((APTR) + (t + 1) * 16);                      \
            bv = *(const float4*)((BPTR) + (t + 1) * 16);                      \
        }                                                                      \
        const float* Ab = As[t & 1];                                           \
        const float* Bb = Bs[t & 1];                                           \
        _Pragma("unroll")                                                      \
        for (int kk = 0; kk < 16; kk += 8) {                                   \
            wmma::load_matrix_sync(b_hi, &Bb[(wn * 16) * TLD + kk], TLD);      \
            split3(b_hi, b_lo);                                                \
            wmma::load_matrix_sync(a_hi, &Ab[(wm * 32) * TLD + kk], TLD);      \
            split3(a_hi, a_lo);                                                \
            wmma::mma_sync(c0, a_lo, b_hi, c0);                                \
            wmma::mma_sync(c0, a_hi, b_lo, c0);                                \
            wmma::mma_sync(c0, a_hi, b_hi, c0);                                \
            wmma::load_matrix_sync(a_hi, &Ab[(wm * 32 + 16) * TLD + kk], TLD); \
            split3(a_hi, a_lo);                                                \
            wmma::mma_sync(c1, a_lo, b_hi, c1);                                \
            wmma::mma_sync(c1, a_hi, b_lo, c1);                                \
            wmma::mma_sync(c1, a_hi, b_hi, c1);                                \
        }                                                                      \
        if (t + 1 < (NT)) {                                                    \
            int nb = (t + 1) & 1;                                              \
            *(float4*)&As[nb][r * TLD + c4] = av;                              \
            *(float4*)&Bs[nb][r * TLD + c4] = bv;                              \
            __syncthreads();                                                   \
        }                                                                      \
    }                                                                          \
    __syncthreads();                                                           \
    wmma::store_matrix_sync(cs + (wm * 32) * CLD + wn * 16, c0, CLD,           \
                            wmma::mem_row_major);                              \
    wmma::store_matrix_sync(cs + (wm * 32 + 16) * CLD + wn * 16, c1, CLD,      \
                            wmma::mem_row_major);                              \
    __syncthreads();

// ---------------------------------------------------------------------------
// K1: prep GEMM (tensor cores, smem-staged 3xTF32).
// Fused M=4096 (rows<2048: keys -> A with W1[:,:256]; else queries -> Ct + b1).
// grid (2 n-tiles, 64 m-tiles) = 128 blocks, 256 threads.
// ---------------------------------------------------------------------------
__global__ void __launch_bounds__(256) prep_wmma(
        const float* __restrict__ queries,
        const float* __restrict__ keys,
        const float* __restrict__ b1) {
    __shared__ __align__(16) float As[2][64 * TLD];
    __shared__ __align__(16) float Bs[2][64 * TLD];
    __shared__ __align__(16) float cs[64 * CLD];

    int m0g = blockIdx.y * 64;
    int side = m0g >= (B_ * TK_);
    int m0 = m0g & (B_ * TK_ - 1);
    int n0 = blockIdx.x * 64;
    const float* X = side ? queries : keys;

    {
        int rr = threadIdx.x >> 2, cc = (threadIdx.x & 3) * 4;
        const float* aptr = X + (m0 + rr) * EMB_ + cc;
        const float* bptr = g_W1p + (n0 + rr) * F2E_ + side * EMB_ + cc;
        GEMM_BODY(aptr, EMB_, bptr, F2E_, EMB_ / 16)
        for (int e = tid; e < 64 * 64; e += 256) {
            int rw = e >> 6, col = e & 63;
            int h = n0 + col;
            if (h < HID_) {
                float v = cs[rw * CLD + col];
                int row = m0 + rw;
                if (!side) {
                    g_A[row * HID_ + h] = v;
                } else {
                    int b = row >> 7, j = row & 127;
                    g_Ct[(b * HID_ + h) * TQ_ + j] = v + b1[h];
                }
            }
        }
    }
}

// ---------------------------------------------------------------------------
// K2: fused score MLP + softmax + attention + feature build (R4 version).
// One block per (b, 8-row i-tile): grid (16, 16) = 256 blocks, 256 threads.
// ---------------------------------------------------------------------------
#define ITILE 8
#define PSTR  12

__global__ void __launch_bounds__(256) attn_kernel(
        const float* __restrict__ queries,
        const float* __restrict__ keys,
        const float* __restrict__ qmask,
        const float* __restrict__ kmask,
        const float* __restrict__ W2) {
    extern __shared__ __align__(16) float sm[];
    float* c_s  = sm;                        // 12800
    float* a_s  = c_s + HID_ * TQ_;          // 800
    float* p_s  = a_s + ITILE * HID_;        // 1536
    float* w2_s = p_s + TQ_ * PSTR;          // 104
    float* km_s = w2_s + 104;                // 8

    int b  = blockIdx.y;
    int i0 = blockIdx.x * ITILE;
    int tid = threadIdx.x;

    {
        const float4* src = (const float4*)(g_Ct + b * HID_ * TQ_);
        float4* dst = (float4*)c_s;
        for (int idx = tid; idx < (HID_ * TQ_) / 4; idx += 256)
            dst[idx] = src[idx];
    }
    for (int idx = tid; idx < ITILE * HID_; idx += 256)
        a_s[idx] = g_A[(b * TK_ + i0) * HID_ + idx];
    if (tid < HID_)  w2_s[tid] = W2[tid];
    if (tid < ITILE) km_s[tid] = kmask[b * TK_ + i0 + tid];

    int j = tid & 127;        // query position
    int g = tid >> 7;         // i-row parity (0/1)
    float qm = qmask[b * TQ_ + j];
    __syncthreads();

    // ---- phase 1: sim[ii][j] = sum_h tanh(a[ii,h] + c[h,j]) * w2[h]
    float acc[4];
    #pragma unroll
    for (int r = 0; r < 4; ++r) acc[r] = 0.f;
    for (int h = 0; h < HID_; ++h) {
        float cj = c_s[h * TQ_ + j];
        float w  = w2_s[h];
        #pragma unroll
        for (int r = 0; r < 4; ++r) {
            float x = a_s[(g + 2 * r) * HID_ + h] + cj;
            acc[r] = fmaf(w, ftanh(x), acc[r]);
        }
    }
    const float NEGC = -4294967295.0f;  // -2^32 + 1
    #pragma unroll
    for (int r = 0; r < 4; ++r)
        p_s[j * PSTR + (g + 2 * r)] = (qm == 0.0f) ? NEGC : acc[r];
    __syncthreads();

    // ---- phase 2: softmax over j; warp w owns row w (8 warps, 8 rows)
    int warp = tid >> 5, lane = tid & 31;
    {
        int ii = warp;
        float v[4];
        float m = -3.4e38f;
        #pragma unroll
        for (int q = 0; q < 4; ++q) {
            v[q] = p_s[(lane + 32 * q) * PSTR + ii];
            m = fmaxf(m, v[q]);
        }
        #pragma unroll
        for (int off = 16; off; off >>= 1)
            m = fmaxf(m, __shfl_xor_sync(0xffffffffu, m, off));
        float ssum = 0.f;
        #pragma unroll
        for (int q = 0; q < 4; ++q) { v[q] = __expf(v[q] - m); ssum += v[q]; }
        #pragma unroll
        for (int off = 16; off; off >>= 1)
            ssum += __shfl_xor_sync(0xffffffffu, ssum, off);
        float scale = km_s[ii] / ssum;   // fold key_mask scalar into p
        #pragma unroll
        for (int q = 0; q < 4; ++q)
            p_s[(lane + 32 * q) * PSTR + ii] = v[q] * scale;
    }
    __syncthreads();

    // ---- phase 3: keys_attn[ii,e] = sum_j p[ii,j] * q[b,j,e]; then features
    int e = tid;  // 0..255
    float ka[ITILE];
    #pragma unroll
    for (int r = 0; r < ITILE; ++r) ka[r] = 0.f;
    const float* qb = queries + b * TQ_ * EMB_ + e;
    #pragma unroll 4
    for (int jj = 0; jj < TQ_; ++jj) {
        float qv = qb[jj * EMB_];
        float pv[ITILE];
        *(float4*)&pv[0] = *(const float4*)&p_s[jj * PSTR + 0];
        *(float4*)&pv[4] = *(const float4*)&p_s[jj * PSTR + 4];
        #pragma unroll
        for (int r = 0; r < ITILE; ++r)
            ka[r] = fmaf(pv[r], qv, ka[r]);
    }
    #pragma unroll
    for (int r = 0; r < ITILE; ++r) {
        int rowg = b * TK_ + i0 + r;
        float kv = keys[rowg * EMB_ + e];
        float fm = ka[r] * kv;
        float d  = ka[r] - kv;
        g_feat[rowg * F2E_ + e]        = fm;
        g_feat[rowg * F2E_ + EMB_ + e] = d * d;
    }
}

// ---------------------------------------------------------------------------
// K3: out = relu(feat[2048,512] @ Wlast[256,512]^T + blast), tensor cores,
// smem-staged 3xTF32. grid (4 n-tiles, 32 m-tiles) = 128 blocks, 256 threads.
// ---------------------------------------------------------------------------
__global__ void __launch_bounds__(256) gemm_wmma(
        const float* __restrict__ Wlast,
        const float* __restrict__ blast,
        float* __restrict__ out) {
    __shared__ __align__(16) float As[2][64 * TLD];
    __shared__ __align__(16) float Bs[2][64 * TLD];
    __shared__ __align__(16) float cs[64 * CLD];

    int m0 = blockIdx.y * 64;
    int n0 = blockIdx.x * 64;

    {
        int rr = threadIdx.x >> 2, cc = (threadIdx.x & 3) * 4;
        const float* aptr = g_feat + (m0 + rr) * F2E_ + cc;
        const float* bptr = Wlast + (n0 + rr) * F2E_ + cc;
        GEMM_BODY(aptr, F2E_, bptr, F2E_, F2E_ / 16)
        for (int e = tid; e < 64 * 64; e += 256) {
            int rw = e >> 6, col = e & 63;
            float v = cs[rw * CLD + col] + blast[n0 + col];
            out[(m0 + rw) * EMB_ + n0 + col] = fmaxf(v, 0.f);
        }
    }
}

// ---------------------------------------------------------------------------
extern "C" void kernel_launch(void* const* d_in, const int* in_sizes, int n_in,
                              void* d_out, int out_size) {
    const float* queries = (const float*)d_in[0];
    const float* keys    = (const float*)d_in[1];
    const float* qmask   = (const float*)d_in[2];
    const float* kmask   = (const float*)d_in[3];
    const float* W1      = (const float*)d_in[4];
    const float* b1      = (const float*)d_in[5];
    const float* W2      = (const float*)d_in[6];
    const float* Wlast   = (const float*)d_in[7];
    const float* blast   = (const float*)d_in[8];
    float* out = (float*)d_out;

    const int smem_attn = (HID_ * TQ_ + ITILE * HID_ + TQ_ * PSTR + 104 + ITILE) * 4;
    cudaFuncSetAttribute(attn_kernel, cudaFuncAttributeMaxDynamicSharedMemorySize,
                         smem_attn);

    pad_w1<<<256, 256>>>(W1);
    prep_wmma<<<dim3(2, (2 * B_ * TK_) / 64), 256>>>(queries, keys, b1);
    attn_kernel<<<dim3(TK_ / ITILE, B_), 256, smem_attn>>>(queries, keys, qmask,
                                                           kmask, W2);
    gemm_wmma<<<dim3(EMB_ / 64, (B_ * TK_) / 64), 256>>>(Wlast, blast, out);
}

// round 8
// speedup vs baseline: 1.4062x; 1.3323x over previous
#include <cuda_runtime.h>
#include <cuda_bf16.h>
#include <mma.h>
using namespace nvcuda;

#define B_    16
#define TQ_   128
#define TK_   128
#define EMB_  256
#define HID_  100
#define F2E_  512   // 2*EMB
#define MROWS (B_ * TK_)          // 2048
#define XROWS (2 * MROWS)         // 4096 fused (keys || queries)

// Scratch (allocation-free rule: __device__ globals)
__device__ float g_A[MROWS * HID_];            // A[b][i][h]
__device__ float g_Ct[B_ * HID_ * TQ_];        // C^T[b][h][j] (includes +b1)
__device__ __nv_bfloat16 g_Xhi[XROWS * EMB_];  // split keys||queries
__device__ __nv_bfloat16 g_Xlo[XROWS * EMB_];
__device__ __nv_bfloat16 g_W1hi[128 * F2E_];   // W1 padded to 128 rows, split
__device__ __nv_bfloat16 g_W1lo[128 * F2E_];
__device__ __nv_bfloat16 g_Wlhi[EMB_ * F2E_];  // Wlast split
__device__ __nv_bfloat16 g_Wllo[EMB_ * F2E_];
__device__ __nv_bfloat16 g_fhi[MROWS * F2E_];  // features split
__device__ __nv_bfloat16 g_flo[MROWS * F2E_];

__device__ __forceinline__ float ftanh(float x) {
    float y;
    asm("tanh.approx.f32 %0, %1;" : "=f"(y) : "f"(x));
    return y;
}

__device__ __forceinline__ void bsplit(float v, __nv_bfloat16& hi,
                                       __nv_bfloat16& lo) {
    hi = __float2bfloat16(v);
    lo = __float2bfloat16(v - __bfloat162float(hi));
}

// ---------------------------------------------------------------------------
// K0a: split keys||queries into bf16 hi/lo. grid 1024 x 256 thr, 4 elem/thr.
// ---------------------------------------------------------------------------
__global__ void split_inputs(const float* __restrict__ queries,
                             const float* __restrict__ keys) {
    int i = (blockIdx.x * 256 + threadIdx.x) * 4;   // < 4096*256
    float4 v = (i < MROWS * EMB_)
                   ? *(const float4*)(keys + i)
                   : *(const float4*)(queries + i - MROWS * EMB_);
    __nv_bfloat16 h0, h1, h2, h3, l0, l1, l2, l3;
    bsplit(v.x, h0, l0); bsplit(v.y, h1, l1);
    bsplit(v.z, h2, l2); bsplit(v.w, h3, l3);
    *(__nv_bfloat162*)(g_Xhi + i)     = __nv_bfloat162{h0, h1};
    *(__nv_bfloat162*)(g_Xhi + i + 2) = __nv_bfloat162{h2, h3};
    *(__nv_bfloat162*)(g_Xlo + i)     = __nv_bfloat162{l0, l1};
    *(__nv_bfloat162*)(g_Xlo + i + 2) = __nv_bfloat162{l2, l3};
}

// ---------------------------------------------------------------------------
// K0b: split W1 (pad 100->128 rows) and Wlast. grid 768 x 256 thr.
// ---------------------------------------------------------------------------
__global__ void split_weights(const float* __restrict__ W1,
                              const float* __restrict__ Wlast) {
    int i = blockIdx.x * 256 + threadIdx.x;         // < 196608
    if (i < 128 * F2E_) {
        int h = i >> 9;
        float v = (h < HID_) ? W1[i] : 0.f;
        bsplit(v, g_W1hi[i], g_W1lo[i]);
    } else {
        int j = i - 128 * F2E_;
        bsplit(Wlast[j], g_Wlhi[j], g_Wllo[j]);
    }
}

// ---------------------------------------------------------------------------
// bf16 hi/lo GEMM tiles: BM=32, BN=64, BK=32, 256 thr, 8 warps (2m x 4n),
// one 16x16 C tile per warp, 3 MMAs (hh, hl, lh) per k16, double-buffered.
// ---------------------------------------------------------------------------
#define ALD 48   // smem ldm for A tiles (elements; 96B rows)
#define BLD 48   // smem ldm for B tiles
#define CLD 68

typedef wmma::fragment<wmma::matrix_a, 16, 16, 16, __nv_bfloat16,
                       wmma::row_major> FragA;
typedef wmma::fragment<wmma::matrix_b, 16, 16, 16, __nv_bfloat16,
                       wmma::col_major> FragB;
typedef wmma::fragment<wmma::accumulator, 16, 16, 16, float> FragC;

// ---------------------------------------------------------------------------
// K1: prep GEMM. Fused M=4096 rows (keys -> g_A; queries -> g_Ct + b1).
// grid (2 n-tiles, 128 m-tiles) = 256 blocks.
// ---------------------------------------------------------------------------
__global__ void __launch_bounds__(256) prep_bf16(const float* __restrict__ b1) {
    __shared__ __align__(16) __nv_bfloat16 Ah[2][32 * ALD], Al[2][32 * ALD];
    __shared__ __align__(16) __nv_bfloat16 Bh[2][64 * BLD], Bl[2][64 * BLD];
    __shared__ __align__(16) float cs[32 * CLD];

    int m0g = blockIdx.y * 32;
    int side = m0g >= MROWS;
    int n0 = blockIdx.x * 64;
    int tid = threadIdx.x;
    int ar = tid >> 3, ac = (tid & 7) * 4;   // A stage: 32 rows x 32 k
    int br = tid >> 2, bc = (tid & 3) * 8;   // B stage: 64 rows x 32 k
    int w = tid >> 5, wm = w & 1, wn = w >> 1;

    const __nv_bfloat16* Ah_src = g_Xhi + (m0g + ar) * EMB_ + ac;
    const __nv_bfloat16* Al_src = g_Xlo + (m0g + ar) * EMB_ + ac;
    const __nv_bfloat16* Bh_src = g_W1hi + (n0 + br) * F2E_ + side * EMB_ + bc;
    const __nv_bfloat16* Bl_src = g_W1lo + (n0 + br) * F2E_ + side * EMB_ + bc;

    FragC c;
    wmma::fill_fragment(c, 0.f);
    FragA a_hi, a_lo;
    FragB b_hi, b_lo;

    uint2 avh = *(const uint2*)Ah_src;
    uint2 avl = *(const uint2*)Al_src;
    uint4 bvh = *(const uint4*)Bh_src;
    uint4 bvl = *(const uint4*)Bl_src;
    *(uint2*)&Ah[0][ar * ALD + ac] = avh;
    *(uint2*)&Al[0][ar * ALD + ac] = avl;
    *(uint4*)&Bh[0][br * BLD + bc] = bvh;
    *(uint4*)&Bl[0][br * BLD + bc] = bvl;
    __syncthreads();

    const int NT = EMB_ / 32;  // 8
    #pragma unroll 1
    for (int t = 0; t < NT; ++t) {
        if (t + 1 < NT) {
            avh = *(const uint2*)(Ah_src + (t + 1) * 32);
            avl = *(const uint2*)(Al_src + (t + 1) * 32);
            bvh = *(const uint4*)(Bh_src + (t + 1) * 32);
            bvl = *(const uint4*)(Bl_src + (t + 1) * 32);
        }
        int bsel = t & 1;
        #pragma unroll
        for (int kk = 0; kk < 32; kk += 16) {
            wmma::load_matrix_sync(a_hi, &Ah[bsel][(wm * 16) * ALD + kk], ALD);
            wmma::load_matrix_sync(a_lo, &Al[bsel][(wm * 16) * ALD + kk], ALD);
            wmma::load_matrix_sync(b_hi, &Bh[bsel][(wn * 16) * BLD + kk], BLD);
            wmma::load_matrix_sync(b_lo, &Bl[bsel][(wn * 16) * BLD + kk], BLD);
            wmma::mma_sync(c, a_hi, b_hi, c);
            wmma::mma_sync(c, a_hi, b_lo, c);
            wmma::mma_sync(c, a_lo, b_hi, c);
        }
        if (t + 1 < NT) {
            int nb = (t + 1) & 1;
            *(uint2*)&Ah[nb][ar * ALD + ac] = avh;
            *(uint2*)&Al[nb][ar * ALD + ac] = avl;
            *(uint4*)&Bh[nb][br * BLD + bc] = bvh;
            *(uint4*)&Bl[nb][br * BLD + bc] = bvl;
            __syncthreads();
        }
    }
    __syncthreads();
    wmma::store_matrix_sync(cs + (wm * 16) * CLD + wn * 16, c, CLD,
                            wmma::mem_row_major);
    __syncthreads();

    for (int e = tid; e < 32 * 64; e += 256) {
        int rw = e >> 6, col = e & 63;
        int h = n0 + col;
        if (h < HID_) {
            float v = cs[rw * CLD + col];
            int row = (m0g & (MROWS - 1)) + rw;
            if (!side) {
                g_A[row * HID_ + h] = v;
            } else {
                int b = row >> 7, j = row & 127;
                g_Ct[(b * HID_ + h) * TQ_ + j] = v + b1[h];
            }
        }
    }
}

// ---------------------------------------------------------------------------
// K2: fused score MLP + softmax + attention + feature build.
// One block per (b, 8-row i-tile): grid (16, 16), 256 threads.
// Writes features as bf16 hi/lo.
// ---------------------------------------------------------------------------
#define ITILE 8
#define PSTR  12

__global__ void __launch_bounds__(256) attn_kernel(
        const float* __restrict__ queries,
        const float* __restrict__ keys,
        const float* __restrict__ qmask,
        const float* __restrict__ kmask,
        const float* __restrict__ W2) {
    extern __shared__ __align__(16) float sm[];
    float* c_s  = sm;                        // 12800
    float* a_s  = c_s + HID_ * TQ_;          // 800
    float* p_s  = a_s + ITILE * HID_;        // 1536
    float* w2_s = p_s + TQ_ * PSTR;          // 104
    float* km_s = w2_s + 104;                // 8

    int b  = blockIdx.y;
    int i0 = blockIdx.x * ITILE;
    int tid = threadIdx.x;

    {
        const float4* src = (const float4*)(g_Ct + b * HID_ * TQ_);
        float4* dst = (float4*)c_s;
        for (int idx = tid; idx < (HID_ * TQ_) / 4; idx += 256)
            dst[idx] = src[idx];
    }
    for (int idx = tid; idx < ITILE * HID_; idx += 256)
        a_s[idx] = g_A[(b * TK_ + i0) * HID_ + idx];
    if (tid < HID_)  w2_s[tid] = W2[tid];
    if (tid < ITILE) km_s[tid] = kmask[b * TK_ + i0 + tid];

    int j = tid & 127;        // query position
    int g = tid >> 7;         // i-row parity (0/1)
    float qm = qmask[b * TQ_ + j];
    __syncthreads();

    // ---- phase 1: sim[ii][j] = sum_h tanh(a[ii,h] + c[h,j]) * w2[h]
    float acc[4];
    #pragma unroll
    for (int r = 0; r < 4; ++r) acc[r] = 0.f;
    for (int h = 0; h < HID_; ++h) {
        float cj = c_s[h * TQ_ + j];
        float w  = w2_s[h];
        #pragma unroll
        for (int r = 0; r < 4; ++r) {
            float x = a_s[(g + 2 * r) * HID_ + h] + cj;
            acc[r] = fmaf(w, ftanh(x), acc[r]);
        }
    }
    const float NEGC = -4294967295.0f;  // -2^32 + 1
    #pragma unroll
    for (int r = 0; r < 4; ++r)
        p_s[j * PSTR + (g + 2 * r)] = (qm == 0.0f) ? NEGC : acc[r];
    __syncthreads();

    // ---- phase 2: softmax over j; warp w owns row w (8 warps, 8 rows)
    int warp = tid >> 5, lane = tid & 31;
    {
        int ii = warp;
        float v[4];
        float m = -3.4e38f;
        #pragma unroll
        for (int q = 0; q < 4; ++q) {
            v[q] = p_s[(lane + 32 * q) * PSTR + ii];
            m = fmaxf(m, v[q]);
        }
        #pragma unroll
        for (int off = 16; off; off >>= 1)
            m = fmaxf(m, __shfl_xor_sync(0xffffffffu, m, off));
        float ssum = 0.f;
        #pragma unroll
        for (int q = 0; q < 4; ++q) { v[q] = __expf(v[q] - m); ssum += v[q]; }
        #pragma unroll
        for (int off = 16; off; off >>= 1)
            ssum += __shfl_xor_sync(0xffffffffu, ssum, off);
        float scale = km_s[ii] / ssum;   // fold key_mask scalar into p
        #pragma unroll
        for (int q = 0; q < 4; ++q)
            p_s[(lane + 32 * q) * PSTR + ii] = v[q] * scale;
    }
    __syncthreads();

    // ---- phase 3: keys_attn[ii,e] = sum_j p[ii,j] * q[b,j,e]; then features
    int e = tid;  // 0..255
    float ka[ITILE];
    #pragma unroll
    for (int r = 0; r < ITILE; ++r) ka[r] = 0.f;
    const float* qb = queries + b * TQ_ * EMB_ + e;
    #pragma unroll 4
    for (int jj = 0; jj < TQ_; ++jj) {
        float qv = qb[jj * EMB_];
        float pv[ITILE];
        *(float4*)&pv[0] = *(const float4*)&p_s[jj * PSTR + 0];
        *(float4*)&pv[4] = *(const float4*)&p_s[jj * PSTR + 4];
        #pragma unroll
        for (int r = 0; r < ITILE; ++r)
            ka[r] = fmaf(pv[r], qv, ka[r]);
    }
    #pragma unroll
    for (int r = 0; r < ITILE; ++r) {
        int rowg = b * TK_ + i0 + r;
        float kv = keys[rowg * EMB_ + e];
        float fm = ka[r] * kv;
        float d  = ka[r] - kv;
        float fs = d * d;
        __nv_bfloat16 hi, lo;
        bsplit(fm, hi, lo);
        g_fhi[rowg * F2E_ + e] = hi;
        g_flo[rowg * F2E_ + e] = lo;
        bsplit(fs, hi, lo);
        g_fhi[rowg * F2E_ + EMB_ + e] = hi;
        g_flo[rowg * F2E_ + EMB_ + e] = lo;
    }
}

// ---------------------------------------------------------------------------
// K3: out = relu(feat[2048,512] @ Wlast[256,512]^T + blast).
// grid (4 n-tiles, 64 m-tiles) = 256 blocks.
// ---------------------------------------------------------------------------
__global__ void __launch_bounds__(256) gemm_bf16(
        const float* __restrict__ blast,
        float* __restrict__ out) {
    __shared__ __align__(16) __nv_bfloat16 Ah[2][32 * ALD], Al[2][32 * ALD];
    __shared__ __align__(16) __nv_bfloat16 Bh[2][64 * BLD], Bl[2][64 * BLD];
    __shared__ __align__(16) float cs[32 * CLD];

    int m0 = blockIdx.y * 32;
    int n0 = blockIdx.x * 64;
    int tid = threadIdx.x;
    int ar = tid >> 3, ac = (tid & 7) * 4;
    int br = tid >> 2, bc = (tid & 3) * 8;
    int w = tid >> 5, wm = w & 1, wn = w >> 1;

    const __nv_bfloat16* Ah_src = g_fhi + (m0 + ar) * F2E_ + ac;
    const __nv_bfloat16* Al_src = g_flo + (m0 + ar) * F2E_ + ac;
    const __nv_bfloat16* Bh_src = g_Wlhi + (n0 + br) * F2E_ + bc;
    const __nv_bfloat16* Bl_src = g_Wllo + (n0 + br) * F2E_ + bc;

    FragC c;
    wmma::fill_fragment(c, 0.f);
    FragA a_hi, a_lo;
    FragB b_hi, b_lo;

    uint2 avh = *(const uint2*)Ah_src;
    uint2 avl = *(const uint2*)Al_src;
    uint4 bvh = *(const uint4*)Bh_src;
    uint4 bvl = *(const uint4*)Bl_src;
    *(uint2*)&Ah[0][ar * ALD + ac] = avh;
    *(uint2*)&Al[0][ar * ALD + ac] = avl;
    *(uint4*)&Bh[0][br * BLD + bc] = bvh;
    *(uint4*)&Bl[0][br * BLD + bc] = bvl;
    __syncthreads();

    const int NT = F2E_ / 32;  // 16
    #pragma unroll 1
    for (int t = 0; t < NT; ++t) {
        if (t + 1 < NT) {
            avh = *(const uint2*)(Ah_src + (t + 1) * 32);
            avl = *(const uint2*)(Al_src + (t + 1) * 32);
            bvh = *(const uint4*)(Bh_src + (t + 1) * 32);
            bvl = *(const uint4*)(Bl_src + (t + 1) * 32);
        }
        int bsel = t & 1;
        #pragma unroll
        for (int kk = 0; kk < 32; kk += 16) {
            wmma::load_matrix_sync(a_hi, &Ah[bsel][(wm * 16) * ALD + kk], ALD);
            wmma::load_matrix_sync(a_lo, &Al[bsel][(wm * 16) * ALD + kk], ALD);
            wmma::load_matrix_sync(b_hi, &Bh[bsel][(wn * 16) * BLD + kk], BLD);
            wmma::load_matrix_sync(b_lo, &Bl[bsel][(wn * 16) * BLD + kk], BLD);
            wmma::mma_sync(c, a_hi, b_hi, c);
            wmma::mma_sync(c, a_hi, b_lo, c);
            wmma::mma_sync(c, a_lo, b_hi, c);
        }
        if (t + 1 < NT) {
            int nb = (t + 1) & 1;
            *(uint2*)&Ah[nb][ar * ALD + ac] = avh;
            *(uint2*)&Al[nb][ar * ALD + ac] = avl;
            *(uint4*)&Bh[nb][br * BLD + bc] = bvh;
            *(uint4*)&Bl[nb][br * BLD + bc] = bvl;
            __syncthreads();
        }
    }
    __syncthreads();
    wmma::store_matrix_sync(cs + (wm * 16) * CLD + wn * 16, c, CLD,
                            wmma::mem_row_major);
    __syncthreads();

    for (int e = tid; e < 32 * 64; e += 256) {
        int rw = e >> 6, col = e & 63;
        float v = cs[rw * CLD + col] + blast[n0 + col];
        out[(m0 + rw) * EMB_ + n0 + col] = fmaxf(v, 0.f);
    }
}

// ---------------------------------------------------------------------------
extern "C" void kernel_launch(void* const* d_in, const int* in_sizes, int n_in,
                              void* d_out, int out_size) {
    const float* queries = (const float*)d_in[0];
    const float* keys    = (const float*)d_in[1];
    const float* qmask   = (const float*)d_in[2];
    const float* kmask   = (const float*)d_in[3];
    const float* W1      = (const float*)d_in[4];
    const float* b1      = (const float*)d_in[5];
    const float* W2      = (const float*)d_in[6];
    const float* Wlast   = (const float*)d_in[7];
    const float* blast   = (const float*)d_in[8];
    float* out = (float*)d_out;

    const int smem_attn = (HID_ * TQ_ + ITILE * HID_ + TQ_ * PSTR + 104 + ITILE) * 4;
    cudaFuncSetAttribute(attn_kernel, cudaFuncAttributeMaxDynamicSharedMemorySize,
                         smem_attn);

    split_inputs<<<(XROWS * EMB_) / (256 * 4), 256>>>(queries, keys);
    split_weights<<<(128 * F2E_ + EMB_ * F2E_) / 256, 256>>>(W1, Wlast);
    prep_bf16<<<dim3(2, XROWS / 32), 256>>>(b1);
    attn_kernel<<<dim3(TK_ / ITILE, B_), 256, smem_attn>>>(queries, keys, qmask,
                                                           kmask, W2);
    gemm_bf16<<<dim3(EMB_ / 64, MROWS / 32), 256>>>(blast, out);
}

// round 9
// speedup vs baseline: 1.4473x; 1.0293x over previous
#include <cuda_runtime.h>
#include <cuda_bf16.h>
#include <mma.h>
using namespace nvcuda;

#define B_    16
#define TQ_   128
#define TK_   128
#define EMB_  256
#define HID_  100
#define F2E_  512   // 2*EMB
#define MROWS (B_ * TK_)          // 2048
#define XROWS (2 * MROWS)         // 4096 fused (keys || queries)

// Scratch (allocation-free rule: __device__ globals)
__device__ float g_A[MROWS * HID_];            // A[b][i][h]
__device__ float g_Ct[B_ * HID_ * TQ_];        // C^T[b][h][j] (includes +b1)
__device__ __nv_bfloat16 g_Xhi[XROWS * EMB_];  // split keys||queries
__device__ __nv_bfloat16 g_Xlo[XROWS * EMB_];
__device__ __nv_bfloat16 g_W1hi[128 * F2E_];   // W1 padded to 128 rows, split
__device__ __nv_bfloat16 g_W1lo[128 * F2E_];
__device__ __nv_bfloat16 g_Wlhi[EMB_ * F2E_];  // Wlast split
__device__ __nv_bfloat16 g_Wllo[EMB_ * F2E_];
__device__ __nv_bfloat16 g_fhi[MROWS * F2E_];  // features split
__device__ __nv_bfloat16 g_flo[MROWS * F2E_];

__device__ __forceinline__ float ftanh(float x) {
    float y;
    asm("tanh.approx.f32 %0, %1;" : "=f"(y) : "f"(x));
    return y;
}

__device__ __forceinline__ void bsplit(float v, __nv_bfloat16& hi,
                                       __nv_bfloat16& lo) {
    hi = __float2bfloat16(v);
    lo = __float2bfloat16(v - __bfloat162float(hi));
}

// ---------------------------------------------------------------------------
// K0a: split keys||queries into bf16 hi/lo. grid 1024 x 256 thr, 4 elem/thr.
// ---------------------------------------------------------------------------
__global__ void split_inputs(const float* __restrict__ queries,
                             const float* __restrict__ keys) {
    int i = (blockIdx.x * 256 + threadIdx.x) * 4;   // < 4096*256
    float4 v = (i < MROWS * EMB_)
                   ? *(const float4*)(keys + i)
                   : *(const float4*)(queries + i - MROWS * EMB_);
    __nv_bfloat16 h0, h1, h2, h3, l0, l1, l2, l3;
    bsplit(v.x, h0, l0); bsplit(v.y, h1, l1);
    bsplit(v.z, h2, l2); bsplit(v.w, h3, l3);
    *(__nv_bfloat162*)(g_Xhi + i)     = __nv_bfloat162{h0, h1};
    *(__nv_bfloat162*)(g_Xhi + i + 2) = __nv_bfloat162{h2, h3};
    *(__nv_bfloat162*)(g_Xlo + i)     = __nv_bfloat162{l0, l1};
    *(__nv_bfloat162*)(g_Xlo + i + 2) = __nv_bfloat162{l2, l3};
}

// ---------------------------------------------------------------------------
// K0b: split W1 (pad 100->128 rows) and Wlast. grid 768 x 256 thr.
// ---------------------------------------------------------------------------
__global__ void split_weights(const float* __restrict__ W1,
                              const float* __restrict__ Wlast) {
    int i = blockIdx.x * 256 + threadIdx.x;         // < 196608
    if (i < 128 * F2E_) {
        int h = i >> 9;
        float v = (h < HID_) ? W1[i] : 0.f;
        bsplit(v, g_W1hi[i], g_W1lo[i]);
    } else {
        int j = i - 128 * F2E_;
        bsplit(Wlast[j], g_Wlhi[j], g_Wllo[j]);
    }
}

// ---------------------------------------------------------------------------
// bf16 hi/lo GEMM tiles: BM=32, BN=64, BK=32, 256 thr, 8 warps (2m x 4n),
// one 16x16 C tile per warp, 3 MMAs (hh, hl, lh) per k16, double-buffered.
// ---------------------------------------------------------------------------
#define ALD 48
#define BLD 48
#define CLD 68

typedef wmma::fragment<wmma::matrix_a, 16, 16, 16, __nv_bfloat16,
                       wmma::row_major> FragA;
typedef wmma::fragment<wmma::matrix_b, 16, 16, 16, __nv_bfloat16,
                       wmma::col_major> FragB;
typedef wmma::fragment<wmma::accumulator, 16, 16, 16, float> FragC;

// ---------------------------------------------------------------------------
// K1: prep GEMM. Fused M=4096 rows (keys -> g_A; queries -> g_Ct + b1).
// grid (2 n-tiles, 128 m-tiles) = 256 blocks.
// ---------------------------------------------------------------------------
__global__ void __launch_bounds__(256) prep_bf16(const float* __restrict__ b1) {
    __shared__ __align__(16) __nv_bfloat16 Ah[2][32 * ALD], Al[2][32 * ALD];
    __shared__ __align__(16) __nv_bfloat16 Bh[2][64 * BLD], Bl[2][64 * BLD];
    __shared__ __align__(16) float cs[32 * CLD];

    int m0g = blockIdx.y * 32;
    int side = m0g >= MROWS;
    int n0 = blockIdx.x * 64;
    int tid = threadIdx.x;
    int ar = tid >> 3, ac = (tid & 7) * 4;
    int br = tid >> 2, bc = (tid & 3) * 8;
    int w = tid >> 5, wm = w & 1, wn = w >> 1;

    const __nv_bfloat16* Ah_src = g_Xhi + (m0g + ar) * EMB_ + ac;
    const __nv_bfloat16* Al_src = g_Xlo + (m0g + ar) * EMB_ + ac;
    const __nv_bfloat16* Bh_src = g_W1hi + (n0 + br) * F2E_ + side * EMB_ + bc;
    const __nv_bfloat16* Bl_src = g_W1lo + (n0 + br) * F2E_ + side * EMB_ + bc;

    FragC c;
    wmma::fill_fragment(c, 0.f);
    FragA a_hi, a_lo;
    FragB b_hi, b_lo;

    uint2 avh = *(const uint2*)Ah_src;
    uint2 avl = *(const uint2*)Al_src;
    uint4 bvh = *(const uint4*)Bh_src;
    uint4 bvl = *(const uint4*)Bl_src;
    *(uint2*)&Ah[0][ar * ALD + ac] = avh;
    *(uint2*)&Al[0][ar * ALD + ac] = avl;
    *(uint4*)&Bh[0][br * BLD + bc] = bvh;
    *(uint4*)&Bl[0][br * BLD + bc] = bvl;
    __syncthreads();

    const int NT = EMB_ / 32;  // 8
    #pragma unroll 1
    for (int t = 0; t < NT; ++t) {
        if (t + 1 < NT) {
            avh = *(const uint2*)(Ah_src + (t + 1) * 32);
            avl = *(const uint2*)(Al_src + (t + 1) * 32);
            bvh = *(const uint4*)(Bh_src + (t + 1) * 32);
            bvl = *(const uint4*)(Bl_src + (t + 1) * 32);
        }
        int bsel = t & 1;
        #pragma unroll
        for (int kk = 0; kk < 32; kk += 16) {
            wmma::load_matrix_sync(a_hi, &Ah[bsel][(wm * 16) * ALD + kk], ALD);
            wmma::load_matrix_sync(a_lo, &Al[bsel][(wm * 16) * ALD + kk], ALD);
            wmma::load_matrix_sync(b_hi, &Bh[bsel][(wn * 16) * BLD + kk], BLD);
            wmma::load_matrix_sync(b_lo, &Bl[bsel][(wn * 16) * BLD + kk], BLD);
            wmma::mma_sync(c, a_hi, b_hi, c);
            wmma::mma_sync(c, a_hi, b_lo, c);
            wmma::mma_sync(c, a_lo, b_hi, c);
        }
        if (t + 1 < NT) {
            int nb = (t + 1) & 1;
            *(uint2*)&Ah[nb][ar * ALD + ac] = avh;
            *(uint2*)&Al[nb][ar * ALD + ac] = avl;
            *(uint4*)&Bh[nb][br * BLD + bc] = bvh;
            *(uint4*)&Bl[nb][br * BLD + bc] = bvl;
            __syncthreads();
        }
    }
    __syncthreads();
    wmma::store_matrix_sync(cs + (wm * 16) * CLD + wn * 16, c, CLD,
                            wmma::mem_row_major);
    __syncthreads();

    for (int e = tid; e < 32 * 64; e += 256) {
        int rw = e >> 6, col = e & 63;
        int h = n0 + col;
        if (h < HID_) {
            float v = cs[rw * CLD + col];
            int row = (m0g & (MROWS - 1)) + rw;
            if (!side) {
                g_A[row * HID_ + h] = v;
            } else {
                int b = row >> 7, j = row & 127;
                g_Ct[(b * HID_ + h) * TQ_ + j] = v + b1[h];
            }
        }
    }
}

// ---------------------------------------------------------------------------
// K2: fused score MLP + softmax + attention + feature build.
// 512 threads, one block per (b, 8-row i-tile): grid (16, 16).
// a-tile stored TRANSPOSED (a_t[h][8]) so phase 1 reads 2 rows per LDS.64.
// ---------------------------------------------------------------------------
#define ITILE 8
#define PSTR  12

__global__ void __launch_bounds__(512) attn_kernel(
        const float* __restrict__ queries,
        const float* __restrict__ keys,
        const float* __restrict__ qmask,
        const float* __restrict__ kmask,
        const float* __restrict__ W2) {
    extern __shared__ __align__(16) float sm[];
    float* c_s  = sm;                        // 12800
    float* a_t  = c_s + HID_ * TQ_;          // 100*8 = 800 (transposed)
    float* p_s  = a_t + HID_ * ITILE;        // 128*12 = 1536
    float* w2_s = p_s + TQ_ * PSTR;          // 104
    float* km_s = w2_s + 104;                // 8

    int b  = blockIdx.y;
    int i0 = blockIdx.x * ITILE;
    int tid = threadIdx.x;

    {
        const float4* src = (const float4*)(g_Ct + b * HID_ * TQ_);
        float4* dst = (float4*)c_s;
        for (int idx = tid; idx < (HID_ * TQ_) / 4; idx += 512)
            dst[idx] = src[idx];
    }
    // transposed a: a_t[h*8 + r] = A[i0+r][h]
    for (int idx = tid; idx < HID_ * ITILE; idx += 512) {
        int r = idx & 7, h = idx >> 3;
        a_t[h * ITILE + r] = g_A[(b * TK_ + i0 + r) * HID_ + h];
    }
    if (tid < HID_)  w2_s[tid] = W2[tid];
    if (tid < ITILE) km_s[tid] = kmask[b * TK_ + i0 + tid];

    int j = tid & 127;        // query position
    int g = (tid >> 7) & 3;   // row pair id (0..3): rows 2g, 2g+1
    float qm = qmask[b * TQ_ + j];
    __syncthreads();

    // ---- phase 1: sim[ii][j] = sum_h tanh(a[ii,h] + c[h,j]) * w2[h]
    float acc0 = 0.f, acc1 = 0.f;
    #pragma unroll 4
    for (int h = 0; h < HID_; ++h) {
        float cj = c_s[h * TQ_ + j];
        float w  = w2_s[h];
        float2 a2 = *(const float2*)&a_t[h * ITILE + g * 2];
        acc0 = fmaf(w, ftanh(a2.x + cj), acc0);
        acc1 = fmaf(w, ftanh(a2.y + cj), acc1);
    }
    const float NEGC = -4294967295.0f;  // -2^32 + 1
    p_s[j * PSTR + g * 2]     = (qm == 0.0f) ? NEGC : acc0;
    p_s[j * PSTR + g * 2 + 1] = (qm == 0.0f) ? NEGC : acc1;
    __syncthreads();

    // ---- phase 2: softmax over j; warps 0..7 own rows 0..7
    int warp = tid >> 5, lane = tid & 31;
    if (warp < ITILE) {
        int ii = warp;
        float v[4];
        float m = -3.4e38f;
        #pragma unroll
        for (int q = 0; q < 4; ++q) {
            v[q] = p_s[(lane + 32 * q) * PSTR + ii];
            m = fmaxf(m, v[q]);
        }
        #pragma unroll
        for (int off = 16; off; off >>= 1)
            m = fmaxf(m, __shfl_xor_sync(0xffffffffu, m, off));
        float ssum = 0.f;
        #pragma unroll
        for (int q = 0; q < 4; ++q) { v[q] = __expf(v[q] - m); ssum += v[q]; }
        #pragma unroll
        for (int off = 16; off; off >>= 1)
            ssum += __shfl_xor_sync(0xffffffffu, ssum, off);
        float scale = km_s[ii] / ssum;   // fold key_mask scalar into p
        #pragma unroll
        for (int q = 0; q < 4; ++q)
            p_s[(lane + 32 * q) * PSTR + ii] = v[q] * scale;
    }
    __syncthreads();

    // ---- phase 3: keys_attn[ii,e] = sum_j p[ii,j] * q[b,j,e]; then features
    int e = tid & 255;        // emb index
    int half = tid >> 8;      // 0: rows 0..3, 1: rows 4..7
    float ka[4];
    #pragma unroll
    for (int r = 0; r < 4; ++r) ka[r] = 0.f;
    const float* qb = queries + b * TQ_ * EMB_ + e;
    #pragma unroll 4
    for (int jj = 0; jj < TQ_; ++jj) {
        float qv = qb[jj * EMB_];
        float4 pv = *(const float4*)&p_s[jj * PSTR + half * 4];
        ka[0] = fmaf(pv.x, qv, ka[0]);
        ka[1] = fmaf(pv.y, qv, ka[1]);
        ka[2] = fmaf(pv.z, qv, ka[2]);
        ka[3] = fmaf(pv.w, qv, ka[3]);
    }
    #pragma unroll
    for (int r = 0; r < 4; ++r) {
        int rowg = b * TK_ + i0 + half * 4 + r;
        float kv = keys[rowg * EMB_ + e];
        float fm = ka[r] * kv;
        float d  = ka[r] - kv;
        float fs = d * d;
        __nv_bfloat16 hi, lo;
        bsplit(fm, hi, lo);
        g_fhi[rowg * F2E_ + e] = hi;
        g_flo[rowg * F2E_ + e] = lo;
        bsplit(fs, hi, lo);
        g_fhi[rowg * F2E_ + EMB_ + e] = hi;
        g_flo[rowg * F2E_ + EMB_ + e] = lo;
    }
}

// ---------------------------------------------------------------------------
// K3: out = relu(feat[2048,512] @ Wlast[256,512]^T + blast).
// grid (4 n-tiles, 64 m-tiles) = 256 blocks.
// ---------------------------------------------------------------------------
__global__ void __launch_bounds__(256) gemm_bf16(
        const float* __restrict__ blast,
        float* __restrict__ out) {
    __shared__ __align__(16) __nv_bfloat16 Ah[2][32 * ALD], Al[2][32 * ALD];
    __shared__ __align__(16) __nv_bfloat16 Bh[2][64 * BLD], Bl[2][64 * BLD];
    __shared__ __align__(16) float cs[32 * CLD];

    int m0 = blockIdx.y * 32;
    int n0 = blockIdx.x * 64;
    int tid = threadIdx.x;
    int ar = tid >> 3, ac = (tid & 7) * 4;
    int br = tid >> 2, bc = (tid & 3) * 8;
    int w = tid >> 5, wm = w & 1, wn = w >> 1;

    const __nv_bfloat16* Ah_src = g_fhi + (m0 + ar) * F2E_ + ac;
    const __nv_bfloat16* Al_src = g_flo + (m0 + ar) * F2E_ + ac;
    const __nv_bfloat16* Bh_src = g_Wlhi + (n0 + br) * F2E_ + bc;
    const __nv_bfloat16* Bl_src = g_Wllo + (n0 + br) * F2E_ + bc;

    FragC c;
    wmma::fill_fragment(c, 0.f);
    FragA a_hi, a_lo;
    FragB b_hi, b_lo;

    uint2 avh = *(const uint2*)Ah_src;
    uint2 avl = *(const uint2*)Al_src;
    uint4 bvh = *(const uint4*)Bh_src;
    uint4 bvl = *(const uint4*)Bl_src;
    *(uint2*)&Ah[0][ar * ALD + ac] = avh;
    *(uint2*)&Al[0][ar * ALD + ac] = avl;
    *(uint4*)&Bh[0][br * BLD + bc] = bvh;
    *(uint4*)&Bl[0][br * BLD + bc] = bvl;
    __syncthreads();

    const int NT = F2E_ / 32;  // 16
    #pragma unroll 1
    for (int t = 0; t < NT; ++t) {
        if (t + 1 < NT) {
            avh = *(const uint2*)(Ah_src + (t + 1) * 32);
            avl = *(const uint2*)(Al_src + (t + 1) * 32);
            bvh = *(const uint4*)(Bh_src + (t + 1) * 32);
            bvl = *(const uint4*)(Bl_src + (t + 1) * 32);
        }
        int bsel = t & 1;
        #pragma unroll
        for (int kk = 0; kk < 32; kk += 16) {
            wmma::load_matrix_sync(a_hi, &Ah[bsel][(wm * 16) * ALD + kk], ALD);
            wmma::load_matrix_sync(a_lo, &Al[bsel][(wm * 16) * ALD + kk], ALD);
            wmma::load_matrix_sync(b_hi, &Bh[bsel][(wn * 16) * BLD + kk], BLD);
            wmma::load_matrix_sync(b_lo, &Bl[bsel][(wn * 16) * BLD + kk], BLD);
            wmma::mma_sync(c, a_hi, b_hi, c);
            wmma::mma_sync(c, a_hi, b_lo, c);
            wmma::mma_sync(c, a_lo, b_hi, c);
        }
        if (t + 1 < NT) {
            int nb = (t + 1) & 1;
            *(uint2*)&Ah[nb][ar * ALD + ac] = avh;
            *(uint2*)&Al[nb][ar * ALD + ac] = avl;
            *(uint4*)&Bh[nb][br * BLD + bc] = bvh;
            *(uint4*)&Bl[nb][br * BLD + bc] = bvl;
            __syncthreads();
        }
    }
    __syncthreads();
    wmma::store_matrix_sync(cs + (wm * 16) * CLD + wn * 16, c, CLD,
                            wmma::mem_row_major);
    __syncthreads();

    for (int e = tid; e < 32 * 64; e += 256) {
        int rw = e >> 6, col = e & 63;
        float v = cs[rw * CLD + col] + blast[n0 + col];
        out[(m0 + rw) * EMB_ + n0 + col] = fmaxf(v, 0.f);
    }
}

// ---------------------------------------------------------------------------
extern "C" void kernel_launch(void* const* d_in, const int* in_sizes, int n_in,
                              void* d_out, int out_size) {
    const float* queries = (const float*)d_in[0];
    const float* keys    = (const float*)d_in[1];
    const float* qmask   = (const float*)d_in[2];
    const float* kmask   = (const float*)d_in[3];
    const float* W1      = (const float*)d_in[4];
    const float* b1      = (const float*)d_in[5];
    const float* W2      = (const float*)d_in[6];
    const float* Wlast   = (const float*)d_in[7];
    const float* blast   = (const float*)d_in[8];
    float* out = (float*)d_out;

    const int smem_attn = (HID_ * TQ_ + HID_ * ITILE + TQ_ * PSTR + 104 + ITILE) * 4;
    cudaFuncSetAttribute(attn_kernel, cudaFuncAttributeMaxDynamicSharedMemorySize,
                         smem_attn);

    split_inputs<<<(XROWS * EMB_) / (256 * 4), 256>>>(queries, keys);
    split_weights<<<(128 * F2E_ + EMB_ * F2E_) / 256, 256>>>(W1, Wlast);
    prep_bf16<<<dim3(2, XROWS / 32), 256>>>(b1);
    attn_kernel<<<dim3(TK_ / ITILE, B_), 512, smem_attn>>>(queries, keys, qmask,
                                                           kmask, W2);
    gemm_bf16<<<dim3(EMB_ / 64, MROWS / 32), 256>>>(blast, out);
}

// round 10
// speedup vs baseline: 1.4983x; 1.0352x over previous
#include <cuda_runtime.h>
#include <cuda_bf16.h>
#include <mma.h>
using namespace nvcuda;

#define B_    16
#define TQ_   128
#define TK_   128
#define EMB_  256
#define HID_  100
#define F2E_  512   // 2*EMB
#define MROWS (B_ * TK_)          // 2048
#define XROWS (2 * MROWS)         // 4096 fused (keys || queries)

// Scratch (allocation-free rule: __device__ globals)
__device__ float g_A[MROWS * HID_];            // A[b][i][h]
__device__ float g_Ct[B_ * HID_ * TQ_];        // C^T[b][h][j] (includes +b1)
__device__ __nv_bfloat16 g_Xhi[XROWS * EMB_];  // split keys||queries
__device__ __nv_bfloat16 g_Xlo[XROWS * EMB_];
__device__ __nv_bfloat16 g_W1hi[128 * F2E_];   // W1 padded to 128 rows, split
__device__ __nv_bfloat16 g_W1lo[128 * F2E_];
__device__ __nv_bfloat16 g_Wlhi[EMB_ * F2E_];  // Wlast split
__device__ __nv_bfloat16 g_Wllo[EMB_ * F2E_];
__device__ __nv_bfloat16 g_fhi[MROWS * F2E_];  // features split
__device__ __nv_bfloat16 g_flo[MROWS * F2E_];
__device__ __nv_bfloat16 g_Phi[MROWS * TQ_];   // softmax P split
__device__ __nv_bfloat16 g_Plo[MROWS * TQ_];

__device__ __forceinline__ float ftanh(float x) {
    float y;
    asm("tanh.approx.f32 %0, %1;" : "=f"(y) : "f"(x));
    return y;
}

__device__ __forceinline__ void bsplit(float v, __nv_bfloat16& hi,
                                       __nv_bfloat16& lo) {
    hi = __float2bfloat16(v);
    lo = __float2bfloat16(v - __bfloat162float(hi));
}

// ---------------------------------------------------------------------------
// K0a: split keys||queries into bf16 hi/lo.
// ---------------------------------------------------------------------------
__global__ void split_inputs(const float* __restrict__ queries,
                             const float* __restrict__ keys) {
    int i = (blockIdx.x * 256 + threadIdx.x) * 4;
    float4 v = (i < MROWS * EMB_)
                   ? *(const float4*)(keys + i)
                   : *(const float4*)(queries + i - MROWS * EMB_);
    __nv_bfloat16 h0, h1, h2, h3, l0, l1, l2, l3;
    bsplit(v.x, h0, l0); bsplit(v.y, h1, l1);
    bsplit(v.z, h2, l2); bsplit(v.w, h3, l3);
    *(__nv_bfloat162*)(g_Xhi + i)     = __nv_bfloat162{h0, h1};
    *(__nv_bfloat162*)(g_Xhi + i + 2) = __nv_bfloat162{h2, h3};
    *(__nv_bfloat162*)(g_Xlo + i)     = __nv_bfloat162{l0, l1};
    *(__nv_bfloat162*)(g_Xlo + i + 2) = __nv_bfloat162{l2, l3};
}

// ---------------------------------------------------------------------------
// K0b: split W1 (pad 100->128 rows) and Wlast.
// ---------------------------------------------------------------------------
__global__ void split_weights(const float* __restrict__ W1,
                              const float* __restrict__ Wlast) {
    int i = blockIdx.x * 256 + threadIdx.x;
    if (i < 128 * F2E_) {
        int h = i >> 9;
        float v = (h < HID_) ? W1[i] : 0.f;
        bsplit(v, g_W1hi[i], g_W1lo[i]);
    } else {
        int j = i - 128 * F2E_;
        bsplit(Wlast[j], g_Wlhi[j], g_Wllo[j]);
    }
}

#define ALD 48
#define BLD 48
#define CLD 68

typedef wmma::fragment<wmma::matrix_a, 16, 16, 16, __nv_bfloat16,
                       wmma::row_major> FragA;
typedef wmma::fragment<wmma::matrix_b, 16, 16, 16, __nv_bfloat16,
                       wmma::col_major> FragB;
typedef wmma::fragment<wmma::matrix_b, 16, 16, 16, __nv_bfloat16,
                       wmma::row_major> FragBr;
typedef wmma::fragment<wmma::accumulator, 16, 16, 16, float> FragC;

// ---------------------------------------------------------------------------
// K1: prep GEMM. Fused M=4096 rows (keys -> g_A; queries -> g_Ct + b1).
// grid (2 n-tiles, 128 m-tiles) = 256 blocks.
// ---------------------------------------------------------------------------
__global__ void __launch_bounds__(256) prep_bf16(const float* __restrict__ b1) {
    __shared__ __align__(16) __nv_bfloat16 Ah[2][32 * ALD], Al[2][32 * ALD];
    __shared__ __align__(16) __nv_bfloat16 Bh[2][64 * BLD], Bl[2][64 * BLD];
    __shared__ __align__(16) float cs[32 * CLD];

    int m0g = blockIdx.y * 32;
    int side = m0g >= MROWS;
    int n0 = blockIdx.x * 64;
    int tid = threadIdx.x;
    int ar = tid >> 3, ac = (tid & 7) * 4;
    int br = tid >> 2, bc = (tid & 3) * 8;
    int w = tid >> 5, wm = w & 1, wn = w >> 1;

    const __nv_bfloat16* Ah_src = g_Xhi + (m0g + ar) * EMB_ + ac;
    const __nv_bfloat16* Al_src = g_Xlo + (m0g + ar) * EMB_ + ac;
    const __nv_bfloat16* Bh_src = g_W1hi + (n0 + br) * F2E_ + side * EMB_ + bc;
    const __nv_bfloat16* Bl_src = g_W1lo + (n0 + br) * F2E_ + side * EMB_ + bc;

    FragC c;
    wmma::fill_fragment(c, 0.f);
    FragA a_hi, a_lo;
    FragB b_hi, b_lo;

    uint2 avh = *(const uint2*)Ah_src;
    uint2 avl = *(const uint2*)Al_src;
    uint4 bvh = *(const uint4*)Bh_src;
    uint4 bvl = *(const uint4*)Bl_src;
    *(uint2*)&Ah[0][ar * ALD + ac] = avh;
    *(uint2*)&Al[0][ar * ALD + ac] = avl;
    *(uint4*)&Bh[0][br * BLD + bc] = bvh;
    *(uint4*)&Bl[0][br * BLD + bc] = bvl;
    __syncthreads();

    const int NT = EMB_ / 32;  // 8
    #pragma unroll 1
    for (int t = 0; t < NT; ++t) {
        if (t + 1 < NT) {
            avh = *(const uint2*)(Ah_src + (t + 1) * 32);
            avl = *(const uint2*)(Al_src + (t + 1) * 32);
            bvh = *(const uint4*)(Bh_src + (t + 1) * 32);
            bvl = *(const uint4*)(Bl_src + (t + 1) * 32);
        }
        int bsel = t & 1;
        #pragma unroll
        for (int kk = 0; kk < 32; kk += 16) {
            wmma::load_matrix_sync(a_hi, &Ah[bsel][(wm * 16) * ALD + kk], ALD);
            wmma::load_matrix_sync(a_lo, &Al[bsel][(wm * 16) * ALD + kk], ALD);
            wmma::load_matrix_sync(b_hi, &Bh[bsel][(wn * 16) * BLD + kk], BLD);
            wmma::load_matrix_sync(b_lo, &Bl[bsel][(wn * 16) * BLD + kk], BLD);
            wmma::mma_sync(c, a_hi, b_hi, c);
            wmma::mma_sync(c, a_hi, b_lo, c);
            wmma::mma_sync(c, a_lo, b_hi, c);
        }
        if (t + 1 < NT) {
            int nb = (t + 1) & 1;
            *(uint2*)&Ah[nb][ar * ALD + ac] = avh;
            *(uint2*)&Al[nb][ar * ALD + ac] = avl;
            *(uint4*)&Bh[nb][br * BLD + bc] = bvh;
            *(uint4*)&Bl[nb][br * BLD + bc] = bvl;
            __syncthreads();
        }
    }
    __syncthreads();
    wmma::store_matrix_sync(cs + (wm * 16) * CLD + wn * 16, c, CLD,
                            wmma::mem_row_major);
    __syncthreads();

    for (int e = tid; e < 32 * 64; e += 256) {
        int rw = e >> 6, col = e & 63;
        int h = n0 + col;
        if (h < HID_) {
            float v = cs[rw * CLD + col];
            int row = (m0g & (MROWS - 1)) + rw;
            if (!side) {
                g_A[row * HID_ + h] = v;
            } else {
                int b = row >> 7, j = row & 127;
                g_Ct[(b * HID_ + h) * TQ_ + j] = v + b1[h];
            }
        }
    }
}

// ---------------------------------------------------------------------------
// K2a: score MLP + softmax -> P (bf16 hi/lo), km folded in.
// One block per (b, 4-row i-tile): grid (32, 16) = 512 blocks, 256 threads.
// g_Ct is read directly from global (L1-resident; 32 blocks/batch reuse).
// ---------------------------------------------------------------------------
#define ITILE 4
#define PSTR  5

__global__ void __launch_bounds__(256) sim_kernel(
        const float* __restrict__ qmask,
        const float* __restrict__ kmask,
        const float* __restrict__ W2) {
    __shared__ __align__(16) float a_t[HID_ * ITILE];  // transposed A rows
    __shared__ float w2_s[HID_ + 4];
    __shared__ float km_s[ITILE];
    __shared__ float p_s[TQ_ * PSTR];

    int b  = blockIdx.y;
    int i0 = blockIdx.x * ITILE;
    int tid = threadIdx.x;

    for (int idx = tid; idx < HID_ * ITILE; idx += 256) {
        int r = idx & 3, h = idx >> 2;
        a_t[h * ITILE + r] = g_A[(b * TK_ + i0 + r) * HID_ + h];
    }
    if (tid < HID_)  w2_s[tid] = W2[tid];
    if (tid < ITILE) km_s[tid] = kmask[b * TK_ + i0 + tid];

    int j = tid & 127;        // query position
    int g = tid >> 7;         // row pair id (0/1): rows 2g, 2g+1
    float qm = qmask[b * TQ_ + j];
    __syncthreads();

    // ---- phase 1: sim[ii][j] = sum_h tanh(a[ii,h] + c[h,j]) * w2[h]
    const float* cb = g_Ct + b * HID_ * TQ_ + j;
    float acc0 = 0.f, acc1 = 0.f;
    #pragma unroll 4
    for (int h = 0; h < HID_; ++h) {
        float cj = __ldg(cb + h * TQ_);
        float w  = w2_s[h];
        float2 a2 = *(const float2*)&a_t[h * ITILE + g * 2];
        acc0 = fmaf(w, ftanh(a2.x + cj), acc0);
        acc1 = fmaf(w, ftanh(a2.y + cj), acc1);
    }
    const float NEGC = -4294967295.0f;  // -2^32 + 1
    p_s[j * PSTR + g * 2]     = (qm == 0.0f) ? NEGC : acc0;
    p_s[j * PSTR + g * 2 + 1] = (qm == 0.0f) ? NEGC : acc1;
    __syncthreads();

    // ---- phase 2: softmax over j; warps 0..3 own rows 0..3, write P direct
    int warp = tid >> 5, lane = tid & 31;
    if (warp < ITILE) {
        int ii = warp;
        float v[4];
        float m = -3.4e38f;
        #pragma unroll
        for (int q = 0; q < 4; ++q) {
            v[q] = p_s[(lane + 32 * q) * PSTR + ii];
            m = fmaxf(m, v[q]);
        }
        #pragma unroll
        for (int off = 16; off; off >>= 1)
            m = fmaxf(m, __shfl_xor_sync(0xffffffffu, m, off));
        float ssum = 0.f;
        #pragma unroll
        for (int q = 0; q < 4; ++q) { v[q] = __expf(v[q] - m); ssum += v[q]; }
        #pragma unroll
        for (int off = 16; off; off >>= 1)
            ssum += __shfl_xor_sync(0xffffffffu, ssum, off);
        float scale = km_s[ii] / ssum;   // fold key_mask scalar into P
        int prow = (b * TK_ + i0 + ii) * TQ_;
        #pragma unroll
        for (int q = 0; q < 4; ++q) {
            __nv_bfloat16 hi, lo;
            bsplit(v[q] * scale, hi, lo);
            g_Phi[prow + lane + 32 * q] = hi;
            g_Plo[prow + lane + 32 * q] = lo;
        }
    }
}

// ---------------------------------------------------------------------------
// K2b: keys_attn = P @ queries (bf16 hi/lo tensor GEMM, K=128) + feature
// epilogue. M=2048 (key rows), N=256 (emb). grid (4 n-tiles, 64 m-tiles).
// ---------------------------------------------------------------------------
#define PALD 136   // A smem ldm (bf16): 272B rows
#define PBLD 72    // B smem ldm (bf16): 144B rows

__global__ void __launch_bounds__(256) pv_kernel(
        const float* __restrict__ keys) {
    __shared__ __align__(16) __nv_bfloat16 Ah[32 * PALD], Al[32 * PALD];
    __shared__ __align__(16) __nv_bfloat16 Bh[TQ_ * PBLD], Bl[TQ_ * PBLD];
    __shared__ __align__(16) float cs[32 * CLD];

    int m0 = blockIdx.y * 32;          // global key row
    int n0 = blockIdx.x * 64;          // emb col
    int b  = m0 >> 7;
    int tid = threadIdx.x;
    int w = tid >> 5, wm = w & 1, wn = w >> 1;

    // stage A = P[m0..m0+31][0..127] (hi/lo)
    #pragma unroll
    for (int s = 0; s < 2; ++s) {
        int cidx = tid + 256 * s;          // 512 chunks of 8
        int r = cidx >> 4, c8 = (cidx & 15) * 8;
        *(uint4*)&Ah[r * PALD + c8] = *(const uint4*)&g_Phi[(m0 + r) * TQ_ + c8];
        *(uint4*)&Al[r * PALD + c8] = *(const uint4*)&g_Plo[(m0 + r) * TQ_ + c8];
    }
    // stage B = queries_b[0..127][n0..n0+63] (hi/lo), row-major in k
    const __nv_bfloat16* Qh = g_Xhi + (MROWS + b * TQ_) * EMB_ + n0;
    const __nv_bfloat16* Ql = g_Xlo + (MROWS + b * TQ_) * EMB_ + n0;
    #pragma unroll
    for (int s = 0; s < 4; ++s) {
        int cidx = tid + 256 * s;          // 1024 chunks of 8
        int r = cidx >> 3, c8 = (cidx & 7) * 8;
        *(uint4*)&Bh[r * PBLD + c8] = *(const uint4*)(Qh + r * EMB_ + c8);
        *(uint4*)&Bl[r * PBLD + c8] = *(const uint4*)(Ql + r * EMB_ + c8);
    }
    __syncthreads();

    FragC c;
    wmma::fill_fragment(c, 0.f);
    FragA a_hi, a_lo;
    FragBr b_hi, b_lo;
    #pragma unroll
    for (int kk = 0; kk < TQ_; kk += 16) {
        wmma::load_matrix_sync(a_hi, &Ah[(wm * 16) * PALD + kk], PALD);
        wmma::load_matrix_sync(a_lo, &Al[(wm * 16) * PALD + kk], PALD);
        wmma::load_matrix_sync(b_hi, &Bh[kk * PBLD + wn * 16], PBLD);
        wmma::load_matrix_sync(b_lo, &Bl[kk * PBLD + wn * 16], PBLD);
        wmma::mma_sync(c, a_hi, b_hi, c);
        wmma::mma_sync(c, a_hi, b_lo, c);
        wmma::mma_sync(c, a_lo, b_hi, c);
    }
    __syncthreads();
    wmma::store_matrix_sync(cs + (wm * 16) * CLD + wn * 16, c, CLD,
                            wmma::mem_row_major);
    __syncthreads();

    // feature epilogue: fm = ka*kv, fs = (ka-kv)^2, split to bf16
    for (int e = tid; e < 32 * 64; e += 256) {
        int rw = e >> 6, col = e & 63;
        float ka = cs[rw * CLD + col];
        int row = m0 + rw;
        float kv = keys[row * EMB_ + n0 + col];
        float fm = ka * kv;
        float d  = ka - kv;
        float fs = d * d;
        __nv_bfloat16 hi, lo;
        bsplit(fm, hi, lo);
        g_fhi[row * F2E_ + n0 + col] = hi;
        g_flo[row * F2E_ + n0 + col] = lo;
        bsplit(fs, hi, lo);
        g_fhi[row * F2E_ + EMB_ + n0 + col] = hi;
        g_flo[row * F2E_ + EMB_ + n0 + col] = lo;
    }
}

// ---------------------------------------------------------------------------
// K3: out = relu(feat[2048,512] @ Wlast[256,512]^T + blast).
// grid (4 n-tiles, 64 m-tiles) = 256 blocks.
// ---------------------------------------------------------------------------
__global__ void __launch_bounds__(256) gemm_bf16(
        const float* __restrict__ blast,
        float* __restrict__ out) {
    __shared__ __align__(16) __nv_bfloat16 Ah[2][32 * ALD], Al[2][32 * ALD];
    __shared__ __align__(16) __nv_bfloat16 Bh[2][64 * BLD], Bl[2][64 * BLD];
    __shared__ __align__(16) float cs[32 * CLD];

    int m0 = blockIdx.y * 32;
    int n0 = blockIdx.x * 64;
    int tid = threadIdx.x;
    int ar = tid >> 3, ac = (tid & 7) * 4;
    int br = tid >> 2, bc = (tid & 3) * 8;
    int w = tid >> 5, wm = w & 1, wn = w >> 1;

    const __nv_bfloat16* Ah_src = g_fhi + (m0 + ar) * F2E_ + ac;
    const __nv_bfloat16* Al_src = g_flo + (m0 + ar) * F2E_ + ac;
    const __nv_bfloat16* Bh_src = g_Wlhi + (n0 + br) * F2E_ + bc;
    const __nv_bfloat16* Bl_src = g_Wllo + (n0 + br) * F2E_ + bc;

    FragC c;
    wmma::fill_fragment(c, 0.f);
    FragA a_hi, a_lo;
    FragB b_hi, b_lo;

    uint2 avh = *(const uint2*)Ah_src;
    uint2 avl = *(const uint2*)Al_src;
    uint4 bvh = *(const uint4*)Bh_src;
    uint4 bvl = *(const uint4*)Bl_src;
    *(uint2*)&Ah[0][ar * ALD + ac] = avh;
    *(uint2*)&Al[0][ar * ALD + ac] = avl;
    *(uint4*)&Bh[0][br * BLD + bc] = bvh;
    *(uint4*)&Bl[0][br * BLD + bc] = bvl;
    __syncthreads();

    const int NT = F2E_ / 32;  // 16
    #pragma unroll 1
    for (int t = 0; t < NT; ++t) {
        if (t + 1 < NT) {
            avh = *(const uint2*)(Ah_src + (t + 1) * 32);
            avl = *(const uint2*)(Al_src + (t + 1) * 32);
            bvh = *(const uint4*)(Bh_src + (t + 1) * 32);
            bvl = *(const uint4*)(Bl_src + (t + 1) * 32);
        }
        int bsel = t & 1;
        #pragma unroll
        for (int kk = 0; kk < 32; kk += 16) {
            wmma::load_matrix_sync(a_hi, &Ah[bsel][(wm * 16) * ALD + kk], ALD);
            wmma::load_matrix_sync(a_lo, &Al[bsel][(wm * 16) * ALD + kk], ALD);
            wmma::load_matrix_sync(b_hi, &Bh[bsel][(wn * 16) * BLD + kk], BLD);
            wmma::load_matrix_sync(b_lo, &Bl[bsel][(wn * 16) * BLD + kk], BLD);
            wmma::mma_sync(c, a_hi, b_hi, c);
            wmma::mma_sync(c, a_hi, b_lo, c);
            wmma::mma_sync(c, a_lo, b_hi, c);
        }
        if (t + 1 < NT) {
            int nb = (t + 1) & 1;
            *(uint2*)&Ah[nb][ar * ALD + ac] = avh;
            *(uint2*)&Al[nb][ar * ALD + ac] = avl;
            *(uint4*)&Bh[nb][br * BLD + bc] = bvh;
            *(uint4*)&Bl[nb][br * BLD + bc] = bvl;
            __syncthreads();
        }
    }
    __syncthreads();
    wmma::store_matrix_sync(cs + (wm * 16) * CLD + wn * 16, c, CLD,
                            wmma::mem_row_major);
    __syncthreads();

    for (int e = tid; e < 32 * 64; e += 256) {
        int rw = e >> 6, col = e & 63;
        float v = cs[rw * CLD + col] + blast[n0 + col];
        out[(m0 + rw) * EMB_ + n0 + col] = fmaxf(v, 0.f);
    }
}

// ---------------------------------------------------------------------------
extern "C" void kernel_launch(void* const* d_in, const int* in_sizes, int n_in,
                              void* d_out, int out_size) {
    const float* queries = (const float*)d_in[0];
    const float* keys    = (const float*)d_in[1];
    const float* qmask   = (const float*)d_in[2];
    const float* kmask   = (const float*)d_in[3];
    const float* W1      = (const float*)d_in[4];
    const float* b1      = (const float*)d_in[5];
    const float* W2      = (const float*)d_in[6];
    const float* Wlast   = (const float*)d_in[7];
    const float* blast   = (const float*)d_in[8];
    float* out = (float*)d_out;

    split_inputs<<<(XROWS * EMB_) / (256 * 4), 256>>>(queries, keys);
    split_weights<<<(128 * F2E_ + EMB_ * F2E_) / 256, 256>>>(W1, Wlast);
    prep_bf16<<<dim3(2, XROWS / 32), 256>>>(b1);
    sim_kernel<<<dim3(TK_ / ITILE, B_), 256>>>(qmask, kmask, W2);
    pv_kernel<<<dim3(EMB_ / 64, MROWS / 32), 256>>>(keys);
    gemm_bf16<<<dim3(EMB_ / 64, MROWS / 32), 256>>>(blast, out);
}